// round 15
// baseline (speedup 1.0000x reference)
#include <cuda_runtime.h>
#include <cuda_fp16.h>
#include <cstdint>

#define HID  512
#define BATCH 4
#define SEQ  4096

// fp16 intermediates (allocation-free: __device__ globals)
__device__ __half g_xh[(size_t)BATCH * SEQ * HID];       // fp16 copy of x
__device__ __half g_wh[(size_t)3 * HID * HID];           // fp16 Wq|Wk|Wv
__device__ __half g_qk[(size_t)2 * BATCH * SEQ * HID];   // q | k  (contiguous)
__device__ __half g_vt[(size_t)BATCH * HID * SEQ];       // [b][h][s]
__device__ __half g_s [(size_t)BATCH * SEQ * SEQ];       // [b][q][k]

// ---------------------------------------------------------------------------
// helpers
// ---------------------------------------------------------------------------
__device__ __forceinline__ uint32_t packh(float f0, float f1) {
    __half2 h = __floats2half2_rn(f0, f1);
    return *reinterpret_cast<uint32_t*>(&h);
}

__device__ __forceinline__ void mma_hf(float c[4],
                                       uint32_t a0, uint32_t a1, uint32_t a2, uint32_t a3,
                                       uint32_t b0, uint32_t b1) {
    asm volatile(
        "mma.sync.aligned.m16n8k16.row.col.f32.f16.f16.f32 "
        "{%0,%1,%2,%3}, {%4,%5,%6,%7}, {%8,%9}, {%0,%1,%2,%3};\n"
        : "+f"(c[0]), "+f"(c[1]), "+f"(c[2]), "+f"(c[3])
        : "r"(a0), "r"(a1), "r"(a2), "r"(a3), "r"(b0), "r"(b1));
}

__device__ __forceinline__ uint32_t s2u(const void* p) {
    uint32_t a;
    asm("{ .reg .u64 t; cvta.to.shared.u64 t, %1; cvt.u32.u64 %0, t; }"
        : "=r"(a) : "l"(p));
    return a;
}

__device__ __forceinline__ void cpa16(uint32_t dst, const void* src) {
    asm volatile("cp.async.cg.shared.global [%0], [%1], 16;"
                 :: "r"(dst), "l"(src) : "memory");
}

// ---------------------------------------------------------------------------
// fp32 -> fp16 conversion
// ---------------------------------------------------------------------------
__global__ void __launch_bounds__(256) f2h(const float* __restrict__ s,
                                           __half* __restrict__ d, int n) {
    int i = (blockIdx.x * 256 + threadIdx.x) * 4;
    if (i < n) {
        float4 v = *(const float4*)(s + i);
        uint2 u;
        u.x = packh(v.x, v.y);
        u.y = packh(v.z, v.w);
        *(uint2*)(d + i) = u;
    }
}

// three tensors in one launch (z selects source); dst contiguous at stride n
__global__ void __launch_bounds__(256) f2h3(const float* __restrict__ a,
                                            const float* __restrict__ b,
                                            const float* __restrict__ c,
                                            __half* __restrict__ d, int n) {
    const float* s = (blockIdx.z == 0) ? a : (blockIdx.z == 1) ? b : c;
    __half* dst = d + (size_t)blockIdx.z * n;
    int i = (blockIdx.x * 256 + threadIdx.x) * 4;
    if (i < n) {
        float4 v = *(const float4*)(s + i);
        uint2 u;
        u.x = packh(v.x, v.y);
        u.y = packh(v.z, v.w);
        *(uint2*)(dst + i) = u;
    }
}

// ---------------------------------------------------------------------------
// fp16 GEMM NT, cp.async 4-stage pipeline (wait_group 2, 3 loads in flight):
// C[m,n] = sum_k A[m,k]*B[n,k].  BM=BN=128, BK=32 halves (64B rows),
// 128 threads (2x2 warps, warp tile 64x64).
// smem: 4 stages x 256 rows x 80B = 80KB ([row][20w], conflict-free).
// OUTMODE: 0 = fp16 out, 1 = fp32 out (final O),
//          3 = merged QKV: z in {0,1} -> fp16 out at Cv + z*sC_,
//              z==2 -> fp16 transposed into g_vt [b][h][s].
// ---------------------------------------------------------------------------
#define HSTRD 20
#define STAGEB 20480     // (128+128)*80 bytes
#define STAGEW 5120      // words
#define BOFFW  2560      // B offset within stage (128*20)

template<int OUTMODE>
__global__ void __launch_bounds__(128) gemm_h(
    const __half* __restrict__ A, const __half* __restrict__ B, void* __restrict__ Cv,
    int lda, int ldb, int ldc, int Kdim,
    long long sA_, long long sB_, long long sC_)
{
    extern __shared__ __align__(16) uint32_t dsm[];
    const uint32_t sbase = s2u(dsm);

    const __half* Ag = A + (long long)blockIdx.z * sA_ + (long long)blockIdx.y * 128 * lda;
    const __half* Bg = B + (long long)blockIdx.z * sB_ + (long long)blockIdx.x * 128 * ldb;

    const int tid  = threadIdx.x;
    const int warp = tid >> 5, lane = tid & 31;
    const int wm = (warp >> 1) * 64, wn = (warp & 1) * 64;
    const int lr = lane >> 2, lc = lane & 3;

    const int rs = tid >> 2;         // loader row base (0..31)
    const int ps = tid & 3;          // 16B chunk within 64B row

    const int nst = Kdim >> 5;       // K / 32
    float acc[4][8][4] = {};

    auto issue = [&](int s) {
        if (s < nst) {
            const int k0 = s << 5;
            const uint32_t base = sbase + (uint32_t)(s & 3) * STAGEB;
#pragma unroll
            for (int p = 0; p < 4; p++) {
                int row = rs + p * 32;
                cpa16(base + row * 80 + ps * 16,
                      Ag + (long long)row * lda + k0 + ps * 8);
            }
#pragma unroll
            for (int p = 0; p < 4; p++) {
                int row = rs + p * 32;
                cpa16(base + 128 * 80 + row * 80 + ps * 16,
                      Bg + (long long)row * ldb + k0 + ps * 8);
            }
        }
        asm volatile("cp.async.commit_group;" ::: "memory");
    };
    auto compute = [&](int buf) {
        const uint32_t* pA = dsm + buf * STAGEW;
        const uint32_t* pB = pA + BOFFW;
#pragma unroll
        for (int kc = 0; kc < 2; kc++) {
            uint32_t a[4][4];
#pragma unroll
            for (int mi = 0; mi < 4; mi++) {
                int r0 = (wm + mi * 16 + lr) * HSTRD + kc * 8;
                a[mi][0] = pA[r0             + lc    ];
                a[mi][1] = pA[r0 + 8 * HSTRD + lc    ];
                a[mi][2] = pA[r0             + lc + 4];
                a[mi][3] = pA[r0 + 8 * HSTRD + lc + 4];
            }
#pragma unroll
            for (int ni = 0; ni < 8; ni++) {
                int n0 = (wn + ni * 8 + lr) * HSTRD + kc * 8;
                uint32_t b0 = pB[n0 + lc], b1 = pB[n0 + lc + 4];
#pragma unroll
                for (int mi = 0; mi < 4; mi++)
                    mma_hf(acc[mi][ni], a[mi][0], a[mi][1], a[mi][2], a[mi][3], b0, b1);
            }
        }
    };

    issue(0);
    issue(1);
    issue(2);
    for (int s = 0; s < nst; s++) {
        asm volatile("cp.async.wait_group 2;" ::: "memory");
        __syncthreads();
        issue(s + 3);
        compute(s & 3);
    }

    if (OUTMODE == 1) {
        float* Cg = (float*)Cv + (long long)blockIdx.z * sC_
                  + (long long)blockIdx.y * 128 * ldc + (long long)blockIdx.x * 128;
#pragma unroll
        for (int mi = 0; mi < 4; mi++)
#pragma unroll
            for (int ni = 0; ni < 8; ni++) {
                int rr = wm + mi * 16 + lr;
                int cc = wn + ni * 8 + lc * 2;
                *(float2*)(Cg + (long long)rr * ldc + cc)       = make_float2(acc[mi][ni][0], acc[mi][ni][1]);
                *(float2*)(Cg + (long long)(rr + 8) * ldc + cc) = make_float2(acc[mi][ni][2], acc[mi][ni][3]);
            }
    } else if (OUTMODE == 0) {
        __half* Cg = (__half*)Cv + (long long)blockIdx.z * sC_
                   + (long long)blockIdx.y * 128 * ldc + (long long)blockIdx.x * 128;
#pragma unroll
        for (int mi = 0; mi < 4; mi++)
#pragma unroll
            for (int ni = 0; ni < 8; ni++) {
                int rr = wm + mi * 16 + lr;
                int cc = wn + ni * 8 + lc * 2;
                *(uint32_t*)(Cg + (long long)rr * ldc + cc)       = packh(acc[mi][ni][0], acc[mi][ni][1]);
                *(uint32_t*)(Cg + (long long)(rr + 8) * ldc + cc) = packh(acc[mi][ni][2], acc[mi][ni][3]);
            }
    } else {
        // OUTMODE 3: merged QKV
        if (blockIdx.z < 2) {
            __half* Cg = (__half*)Cv + (long long)blockIdx.z * sC_
                       + (long long)blockIdx.y * 128 * ldc + (long long)blockIdx.x * 128;
#pragma unroll
            for (int mi = 0; mi < 4; mi++)
#pragma unroll
                for (int ni = 0; ni < 8; ni++) {
                    int rr = wm + mi * 16 + lr;
                    int cc = wn + ni * 8 + lc * 2;
                    *(uint32_t*)(Cg + (long long)rr * ldc + cc)       = packh(acc[mi][ni][0], acc[mi][ni][1]);
                    *(uint32_t*)(Cg + (long long)(rr + 8) * ldc + cc) = packh(acc[mi][ni][2], acc[mi][ni][3]);
                }
        } else {
            // V projection: transposed write, row R = (b,s), col h -> g_vt[b][h][s]
#pragma unroll
            for (int mi = 0; mi < 4; mi++)
#pragma unroll
                for (int ni = 0; ni < 8; ni++) {
                    int R  = blockIdx.y * 128 + wm + mi * 16 + lr;
                    int hc = blockIdx.x * 128 + wn + ni * 8 + lc * 2;
                    int b  = R >> 12, s = R & (SEQ - 1);
                    __half* base = g_vt + (long long)b * HID * SEQ;
                    base[(long long)hc * SEQ + s]           = __float2half(acc[mi][ni][0]);
                    base[(long long)(hc + 1) * SEQ + s]     = __float2half(acc[mi][ni][1]);
                    base[(long long)hc * SEQ + s + 8]       = __float2half(acc[mi][ni][2]);
                    base[(long long)(hc + 1) * SEQ + s + 8] = __float2half(acc[mi][ni][3]);
                }
        }
    }
}

// ---------------------------------------------------------------------------
// fp16 row softmax over SEQ=4096 with /sqrt(H) scale folded in.
// ---------------------------------------------------------------------------
__global__ void __launch_bounds__(256) softmax_h(__half* __restrict__ S, float scale) {
    long long row = blockIdx.x;
    __half* p = S + row * (long long)SEQ;
    const int tid = threadIdx.x;

    uint4 u[2];
    float f[16];
    float m = -3.4e38f;
#pragma unroll
    for (int i = 0; i < 2; i++) {
        u[i] = ((const uint4*)p)[tid + i * 256];
        const __half2* h = (const __half2*)&u[i];
#pragma unroll
        for (int q = 0; q < 4; q++) {
            float2 g = __half22float2(h[q]);
            f[i * 8 + 2 * q]     = g.x;
            f[i * 8 + 2 * q + 1] = g.y;
            m = fmaxf(m, fmaxf(g.x, g.y));
        }
    }

    __shared__ float red[8];
#pragma unroll
    for (int o = 16; o; o >>= 1) m = fmaxf(m, __shfl_xor_sync(0xffffffffu, m, o));
    if ((tid & 31) == 0) red[tid >> 5] = m;
    __syncthreads();
    m = red[0];
#pragma unroll
    for (int i = 1; i < 8; i++) m = fmaxf(m, red[i]);

    float sum = 0.f;
#pragma unroll
    for (int j = 0; j < 16; j++) {
        f[j] = __expf((f[j] - m) * scale);
        sum += f[j];
    }
#pragma unroll
    for (int o = 16; o; o >>= 1) sum += __shfl_xor_sync(0xffffffffu, sum, o);
    __syncthreads();
    if ((tid & 31) == 0) red[tid >> 5] = sum;
    __syncthreads();
    float tot = 0.f;
#pragma unroll
    for (int i = 0; i < 8; i++) tot += red[i];
    float inv = 1.0f / tot;

#pragma unroll
    for (int i = 0; i < 2; i++) {
        __half2* h = (__half2*)&u[i];
#pragma unroll
        for (int q = 0; q < 4; q++)
            h[q] = __floats2half2_rn(f[i * 8 + 2 * q] * inv, f[i * 8 + 2 * q + 1] * inv);
        ((uint4*)p)[tid + i * 256] = u[i];
    }
}

// ---------------------------------------------------------------------------
// Launcher  (6 kernels total)
// ---------------------------------------------------------------------------
#define SMEMG 81920    // 4 * (128+128) * 80

extern "C" void kernel_launch(void* const* d_in, const int* in_sizes, int n_in,
                              void* d_out, int out_size) {
    const float* x  = (const float*)d_in[0];
    const float* Wq = (const float*)d_in[1];
    const float* Wk = (const float*)d_in[2];
    const float* Wv = (const float*)d_in[3];
    float* out = (float*)d_out;

    __half *xh, *wh, *qkp, *vtp, *sp;
    cudaGetSymbolAddress((void**)&xh,  g_xh);
    cudaGetSymbolAddress((void**)&wh,  g_wh);
    cudaGetSymbolAddress((void**)&qkp, g_qk);
    cudaGetSymbolAddress((void**)&vtp, g_vt);
    cudaGetSymbolAddress((void**)&sp,  g_s);
    __half* qp = qkp;
    __half* kp = qkp + (size_t)BATCH * SEQ * HID;

    cudaFuncSetAttribute(gemm_h<0>, cudaFuncAttributeMaxDynamicSharedMemorySize, SMEMG);
    cudaFuncSetAttribute(gemm_h<1>, cudaFuncAttributeMaxDynamicSharedMemorySize, SMEMG);
    cudaFuncSetAttribute(gemm_h<3>, cudaFuncAttributeMaxDynamicSharedMemorySize, SMEMG);

    // 0) fp32 -> fp16 conversions (2 launches)
    int nx = BATCH * SEQ * HID;
    int nw = HID * HID;
    f2h<<<nx / 1024, 256>>>(x, xh, nx);
    dim3 gw(nw / 1024, 1, 3);
    f2h3<<<gw, 256>>>(Wq, Wk, Wv, wh, nw);

    // 1) merged QKV projections (one launch; z selects W and destination)
    dim3 gq(HID / 128, (BATCH * SEQ) / 128, 3);
    gemm_h<3><<<gq, 128, SMEMG>>>(xh, wh, qp, HID, HID, HID, HID,
                                  0, (long long)HID * HID,
                                  (long long)BATCH * SEQ * HID);

    // 2) S = Q K^T (fp16; BN=128 proven shape; batched M=N=4096, K=512)
    dim3 gs(SEQ / 128, SEQ / 128, BATCH);
    gemm_h<0><<<gs, 128, SMEMG>>>(qp, kp, sp, HID, HID, SEQ, HID,
                                  (long long)SEQ * HID, (long long)SEQ * HID,
                                  (long long)SEQ * SEQ);

    // 3) softmax rows (fp16) with 1/sqrt(H) scale
    softmax_h<<<BATCH * SEQ, 256>>>(sp, 0.044194173824159216f);

    // 4) O = P Vt^T (fp16 in, fp32 out; NT: M=4096, N=512, K=4096)
    dim3 gp(HID / 128, SEQ / 128, BATCH);
    gemm_h<1><<<gp, 128, SMEMG>>>(sp, vtp, out, SEQ, SEQ, HID, SEQ,
                                  (long long)SEQ * SEQ, (long long)HID * SEQ,
                                  (long long)SEQ * HID);
}

// round 16
// speedup vs baseline: 1.1415x; 1.1415x over previous
#include <cuda_runtime.h>
#include <cuda_fp16.h>
#include <cstdint>

#define HID  512
#define BATCH 4
#define SEQ  4096

// fp16 intermediates (allocation-free: __device__ globals)
__device__ __half g_xh[(size_t)BATCH * SEQ * HID];       // fp16 copy of x
__device__ __half g_wh[(size_t)3 * HID * HID];           // fp16 Wq|Wk|Wv
__device__ __half g_qk[(size_t)2 * BATCH * SEQ * HID];   // q | k  (contiguous)
__device__ __half g_vt[(size_t)BATCH * HID * SEQ];       // [b][h][s]
__device__ __half g_s [(size_t)BATCH * SEQ * SEQ];       // [b][q][k]

// ---------------------------------------------------------------------------
// helpers
// ---------------------------------------------------------------------------
__device__ __forceinline__ uint32_t packh(float f0, float f1) {
    __half2 h = __floats2half2_rn(f0, f1);
    return *reinterpret_cast<uint32_t*>(&h);
}

__device__ __forceinline__ void mma_hf(float c[4],
                                       uint32_t a0, uint32_t a1, uint32_t a2, uint32_t a3,
                                       uint32_t b0, uint32_t b1) {
    asm volatile(
        "mma.sync.aligned.m16n8k16.row.col.f32.f16.f16.f32 "
        "{%0,%1,%2,%3}, {%4,%5,%6,%7}, {%8,%9}, {%0,%1,%2,%3};\n"
        : "+f"(c[0]), "+f"(c[1]), "+f"(c[2]), "+f"(c[3])
        : "r"(a0), "r"(a1), "r"(a2), "r"(a3), "r"(b0), "r"(b1));
}

__device__ __forceinline__ uint32_t s2u(const void* p) {
    uint32_t a;
    asm("{ .reg .u64 t; cvta.to.shared.u64 t, %1; cvt.u32.u64 %0, t; }"
        : "=r"(a) : "l"(p));
    return a;
}

__device__ __forceinline__ void cpa16(uint32_t dst, const void* src) {
    asm volatile("cp.async.cg.shared.global [%0], [%1], 16;"
                 :: "r"(dst), "l"(src) : "memory");
}

// ---------------------------------------------------------------------------
// fp32 -> fp16 conversion
// ---------------------------------------------------------------------------
__global__ void __launch_bounds__(256) f2h(const float* __restrict__ s,
                                           __half* __restrict__ d, int n) {
    int i = (blockIdx.x * 256 + threadIdx.x) * 4;
    if (i < n) {
        float4 v = *(const float4*)(s + i);
        uint2 u;
        u.x = packh(v.x, v.y);
        u.y = packh(v.z, v.w);
        *(uint2*)(d + i) = u;
    }
}

// three tensors in one launch (z selects source); dst contiguous at stride n
__global__ void __launch_bounds__(256) f2h3(const float* __restrict__ a,
                                            const float* __restrict__ b,
                                            const float* __restrict__ c,
                                            __half* __restrict__ d, int n) {
    const float* s = (blockIdx.z == 0) ? a : (blockIdx.z == 1) ? b : c;
    __half* dst = d + (size_t)blockIdx.z * n;
    int i = (blockIdx.x * 256 + threadIdx.x) * 4;
    if (i < n) {
        float4 v = *(const float4*)(s + i);
        uint2 u;
        u.x = packh(v.x, v.y);
        u.y = packh(v.z, v.w);
        *(uint2*)(dst + i) = u;
    }
}

// ---------------------------------------------------------------------------
// fp16 GEMM NT, cp.async 3-stage pipeline (wait_group 1, 2 loads in flight):
// C[m,n] = sum_k A[m,k]*B[n,k].  BM=BN=128, BK=32 halves (64B rows),
// 128 threads (2x2 warps, warp tile 64x64).
// smem: 3 stages x 256 rows x 80B = 60KB ([row][20w], conflict-free)
// -> 3 CTAs/SM (12 warps, occ 18%) — the R11-proven fastest shape.
// OUTMODE: 0 = fp16 out, 1 = fp32 out (final O),
//          3 = merged QKV: z in {0,1} -> fp16 out at Cv + z*sC_,
//              z==2 -> fp16 transposed into g_vt [b][h][s].
// ---------------------------------------------------------------------------
#define HSTRD 20
#define STAGEB 20480     // (128+128)*80 bytes
#define STAGEW 5120      // words
#define BOFFW  2560      // B offset within stage (128*20)

template<int OUTMODE>
__global__ void __launch_bounds__(128) gemm_h(
    const __half* __restrict__ A, const __half* __restrict__ B, void* __restrict__ Cv,
    int lda, int ldb, int ldc, int Kdim,
    long long sA_, long long sB_, long long sC_)
{
    extern __shared__ __align__(16) uint32_t dsm[];
    const uint32_t sbase = s2u(dsm);

    const __half* Ag = A + (long long)blockIdx.z * sA_ + (long long)blockIdx.y * 128 * lda;
    const __half* Bg = B + (long long)blockIdx.z * sB_ + (long long)blockIdx.x * 128 * ldb;

    const int tid  = threadIdx.x;
    const int warp = tid >> 5, lane = tid & 31;
    const int wm = (warp >> 1) * 64, wn = (warp & 1) * 64;
    const int lr = lane >> 2, lc = lane & 3;

    const int rs = tid >> 2;         // loader row base (0..31)
    const int ps = tid & 3;          // 16B chunk within 64B row

    const int nst = Kdim >> 5;       // K / 32
    float acc[4][8][4] = {};

    auto issue = [&](int s) {
        if (s < nst) {
            const int k0 = s << 5;
            const uint32_t base = sbase + (uint32_t)(s % 3) * STAGEB;
#pragma unroll
            for (int p = 0; p < 4; p++) {
                int row = rs + p * 32;
                cpa16(base + row * 80 + ps * 16,
                      Ag + (long long)row * lda + k0 + ps * 8);
            }
#pragma unroll
            for (int p = 0; p < 4; p++) {
                int row = rs + p * 32;
                cpa16(base + 128 * 80 + row * 80 + ps * 16,
                      Bg + (long long)row * ldb + k0 + ps * 8);
            }
        }
        asm volatile("cp.async.commit_group;" ::: "memory");
    };
    auto compute = [&](int buf) {
        const uint32_t* pA = dsm + buf * STAGEW;
        const uint32_t* pB = pA + BOFFW;
#pragma unroll
        for (int kc = 0; kc < 2; kc++) {
            uint32_t a[4][4];
#pragma unroll
            for (int mi = 0; mi < 4; mi++) {
                int r0 = (wm + mi * 16 + lr) * HSTRD + kc * 8;
                a[mi][0] = pA[r0             + lc    ];
                a[mi][1] = pA[r0 + 8 * HSTRD + lc    ];
                a[mi][2] = pA[r0             + lc + 4];
                a[mi][3] = pA[r0 + 8 * HSTRD + lc + 4];
            }
#pragma unroll
            for (int ni = 0; ni < 8; ni++) {
                int n0 = (wn + ni * 8 + lr) * HSTRD + kc * 8;
                uint32_t b0 = pB[n0 + lc], b1 = pB[n0 + lc + 4];
#pragma unroll
                for (int mi = 0; mi < 4; mi++)
                    mma_hf(acc[mi][ni], a[mi][0], a[mi][1], a[mi][2], a[mi][3], b0, b1);
            }
        }
    };

    issue(0);
    issue(1);
    for (int s = 0; s < nst; s++) {
        asm volatile("cp.async.wait_group 1;" ::: "memory");
        __syncthreads();
        issue(s + 2);
        compute(s % 3);
    }

    if (OUTMODE == 1) {
        float* Cg = (float*)Cv + (long long)blockIdx.z * sC_
                  + (long long)blockIdx.y * 128 * ldc + (long long)blockIdx.x * 128;
#pragma unroll
        for (int mi = 0; mi < 4; mi++)
#pragma unroll
            for (int ni = 0; ni < 8; ni++) {
                int rr = wm + mi * 16 + lr;
                int cc = wn + ni * 8 + lc * 2;
                *(float2*)(Cg + (long long)rr * ldc + cc)       = make_float2(acc[mi][ni][0], acc[mi][ni][1]);
                *(float2*)(Cg + (long long)(rr + 8) * ldc + cc) = make_float2(acc[mi][ni][2], acc[mi][ni][3]);
            }
    } else if (OUTMODE == 0) {
        __half* Cg = (__half*)Cv + (long long)blockIdx.z * sC_
                   + (long long)blockIdx.y * 128 * ldc + (long long)blockIdx.x * 128;
#pragma unroll
        for (int mi = 0; mi < 4; mi++)
#pragma unroll
            for (int ni = 0; ni < 8; ni++) {
                int rr = wm + mi * 16 + lr;
                int cc = wn + ni * 8 + lc * 2;
                *(uint32_t*)(Cg + (long long)rr * ldc + cc)       = packh(acc[mi][ni][0], acc[mi][ni][1]);
                *(uint32_t*)(Cg + (long long)(rr + 8) * ldc + cc) = packh(acc[mi][ni][2], acc[mi][ni][3]);
            }
    } else {
        // OUTMODE 3: merged QKV
        if (blockIdx.z < 2) {
            __half* Cg = (__half*)Cv + (long long)blockIdx.z * sC_
                       + (long long)blockIdx.y * 128 * ldc + (long long)blockIdx.x * 128;
#pragma unroll
            for (int mi = 0; mi < 4; mi++)
#pragma unroll
                for (int ni = 0; ni < 8; ni++) {
                    int rr = wm + mi * 16 + lr;
                    int cc = wn + ni * 8 + lc * 2;
                    *(uint32_t*)(Cg + (long long)rr * ldc + cc)       = packh(acc[mi][ni][0], acc[mi][ni][1]);
                    *(uint32_t*)(Cg + (long long)(rr + 8) * ldc + cc) = packh(acc[mi][ni][2], acc[mi][ni][3]);
                }
        } else {
            // V projection: transposed write, row R = (b,s), col h -> g_vt[b][h][s]
#pragma unroll
            for (int mi = 0; mi < 4; mi++)
#pragma unroll
                for (int ni = 0; ni < 8; ni++) {
                    int R  = blockIdx.y * 128 + wm + mi * 16 + lr;
                    int hc = blockIdx.x * 128 + wn + ni * 8 + lc * 2;
                    int b  = R >> 12, s = R & (SEQ - 1);
                    __half* base = g_vt + (long long)b * HID * SEQ;
                    base[(long long)hc * SEQ + s]           = __float2half(acc[mi][ni][0]);
                    base[(long long)(hc + 1) * SEQ + s]     = __float2half(acc[mi][ni][1]);
                    base[(long long)hc * SEQ + s + 8]       = __float2half(acc[mi][ni][2]);
                    base[(long long)(hc + 1) * SEQ + s + 8] = __float2half(acc[mi][ni][3]);
                }
        }
    }
}

// ---------------------------------------------------------------------------
// fp16 row softmax over SEQ=4096 with /sqrt(H) scale folded in.
// ---------------------------------------------------------------------------
__global__ void __launch_bounds__(256) softmax_h(__half* __restrict__ S, float scale) {
    long long row = blockIdx.x;
    __half* p = S + row * (long long)SEQ;
    const int tid = threadIdx.x;

    uint4 u[2];
    float f[16];
    float m = -3.4e38f;
#pragma unroll
    for (int i = 0; i < 2; i++) {
        u[i] = ((const uint4*)p)[tid + i * 256];
        const __half2* h = (const __half2*)&u[i];
#pragma unroll
        for (int q = 0; q < 4; q++) {
            float2 g = __half22float2(h[q]);
            f[i * 8 + 2 * q]     = g.x;
            f[i * 8 + 2 * q + 1] = g.y;
            m = fmaxf(m, fmaxf(g.x, g.y));
        }
    }

    __shared__ float red[8];
#pragma unroll
    for (int o = 16; o; o >>= 1) m = fmaxf(m, __shfl_xor_sync(0xffffffffu, m, o));
    if ((tid & 31) == 0) red[tid >> 5] = m;
    __syncthreads();
    m = red[0];
#pragma unroll
    for (int i = 1; i < 8; i++) m = fmaxf(m, red[i]);

    float sum = 0.f;
#pragma unroll
    for (int j = 0; j < 16; j++) {
        f[j] = __expf((f[j] - m) * scale);
        sum += f[j];
    }
#pragma unroll
    for (int o = 16; o; o >>= 1) sum += __shfl_xor_sync(0xffffffffu, sum, o);
    __syncthreads();
    if ((tid & 31) == 0) red[tid >> 5] = sum;
    __syncthreads();
    float tot = 0.f;
#pragma unroll
    for (int i = 0; i < 8; i++) tot += red[i];
    float inv = 1.0f / tot;

#pragma unroll
    for (int i = 0; i < 2; i++) {
        __half2* h = (__half2*)&u[i];
#pragma unroll
        for (int q = 0; q < 4; q++)
            h[q] = __floats2half2_rn(f[i * 8 + 2 * q] * inv, f[i * 8 + 2 * q + 1] * inv);
        ((uint4*)p)[tid + i * 256] = u[i];
    }
}

// ---------------------------------------------------------------------------
// Launcher  (6 kernels total)
// ---------------------------------------------------------------------------
#define SMEMG 61440    // 3 * (128+128) * 80

extern "C" void kernel_launch(void* const* d_in, const int* in_sizes, int n_in,
                              void* d_out, int out_size) {
    const float* x  = (const float*)d_in[0];
    const float* Wq = (const float*)d_in[1];
    const float* Wk = (const float*)d_in[2];
    const float* Wv = (const float*)d_in[3];
    float* out = (float*)d_out;

    __half *xh, *wh, *qkp, *vtp, *sp;
    cudaGetSymbolAddress((void**)&xh,  g_xh);
    cudaGetSymbolAddress((void**)&wh,  g_wh);
    cudaGetSymbolAddress((void**)&qkp, g_qk);
    cudaGetSymbolAddress((void**)&vtp, g_vt);
    cudaGetSymbolAddress((void**)&sp,  g_s);
    __half* qp = qkp;
    __half* kp = qkp + (size_t)BATCH * SEQ * HID;

    cudaFuncSetAttribute(gemm_h<0>, cudaFuncAttributeMaxDynamicSharedMemorySize, SMEMG);
    cudaFuncSetAttribute(gemm_h<1>, cudaFuncAttributeMaxDynamicSharedMemorySize, SMEMG);
    cudaFuncSetAttribute(gemm_h<3>, cudaFuncAttributeMaxDynamicSharedMemorySize, SMEMG);

    // 0) fp32 -> fp16 conversions (2 launches)
    int nx = BATCH * SEQ * HID;
    int nw = HID * HID;
    f2h<<<nx / 1024, 256>>>(x, xh, nx);
    dim3 gw(nw / 1024, 1, 3);
    f2h3<<<gw, 256>>>(Wq, Wk, Wv, wh, nw);

    // 1) merged QKV projections (one launch; z selects W and destination)
    dim3 gq(HID / 128, (BATCH * SEQ) / 128, 3);
    gemm_h<3><<<gq, 128, SMEMG>>>(xh, wh, qp, HID, HID, HID, HID,
                                  0, (long long)HID * HID,
                                  (long long)BATCH * SEQ * HID);

    // 2) S = Q K^T (fp16; BN=128 3-stage proven shape; batched M=N=4096, K=512)
    dim3 gs(SEQ / 128, SEQ / 128, BATCH);
    gemm_h<0><<<gs, 128, SMEMG>>>(qp, kp, sp, HID, HID, SEQ, HID,
                                  (long long)SEQ * HID, (long long)SEQ * HID,
                                  (long long)SEQ * SEQ);

    // 3) softmax rows (fp16) with 1/sqrt(H) scale
    softmax_h<<<BATCH * SEQ, 256>>>(sp, 0.044194173824159216f);

    // 4) O = P Vt^T (fp16 in, fp32 out; NT: M=4096, N=512, K=4096)
    dim3 gp(HID / 128, SEQ / 128, BATCH);
    gemm_h<1><<<gp, 128, SMEMG>>>(sp, vtp, out, SEQ, SEQ, HID, SEQ,
                                  (long long)SEQ * SEQ, (long long)HID * SEQ,
                                  (long long)SEQ * HID);
}